// round 15
// baseline (speedup 1.0000x reference)
#include <cuda_runtime.h>
#include <cuda_fp16.h>
#include <math.h>
#include <stdint.h>

#define N_NODES 10000
#define N_EDGES 640000
#define FDIM    128
#define TILE_E  64
#define N_TILES (N_EDGES / TILE_E)   // 10000

#define LDA 264   // smem stride (fp16) for A tile: 256 + 8
#define LDH 136   // smem stride (fp16) for h tile: 128 + 8
#define ABUF (TILE_E * LDA * 2)      // 33792 bytes per A buffer

// ---- smem map (bytes), per CTA ~84.5KB -> 2 CTAs/SM ----
#define SM_ROW   0                    // 2 x 64 ints (ping-pong)
#define SM_B1    512
#define SM_B2    1024
#define SM_A     1536                 // 2 x ABUF
#define SM_H     (SM_A + 2 * ABUF)    // 69120
#define SM_TOTAL (SM_H + TILE_E * LDH * 2)   // 86528

// ===========================================================================
__device__ float  g_agg[N_NODES * FDIM];
__device__ __half gF[N_NODES * FDIM];
__device__ uint2 gW1f[256 * 32];
__device__ uint2 gW2f[128 * 32];

typedef unsigned long long u64;

__device__ __forceinline__ float sigmoidf_(float x) { return 1.0f / (1.0f + __expf(-x)); }
__device__ __forceinline__ float softsignf_(float x) { return x / (1.0f + fabsf(x)); }

__device__ __forceinline__ uint32_t smem_u32(const void* p) {
    uint32_t a;
    asm("{ .reg .u64 t; cvta.to.shared.u64 t, %1; cvt.u32.u64 %0, t; }" : "=r"(a) : "l"(p));
    return a;
}
__device__ __forceinline__ uint32_t pack_h2(__half lo, __half hi) {
    __half2 v; v.x = lo; v.y = hi;
    return *(uint32_t*)&v;
}
__device__ __forceinline__ void mma_f16(float4& d, const uint32_t a[4], uint2 b) {
    asm volatile(
        "mma.sync.aligned.m16n8k16.row.col.f32.f16.f16.f32 "
        "{%0,%1,%2,%3}, {%4,%5,%6,%7}, {%8,%9}, {%0,%1,%2,%3};"
        : "+f"(d.x), "+f"(d.y), "+f"(d.z), "+f"(d.w)
        : "r"(a[0]), "r"(a[1]), "r"(a[2]), "r"(a[3]), "r"(b.x), "r"(b.y));
}
__device__ __forceinline__ void ldmx4(uint32_t r[4], uint32_t addr) {
    asm volatile("ldmatrix.sync.aligned.m8n8.x4.shared.b16 {%0,%1,%2,%3}, [%4];"
                 : "=r"(r[0]), "=r"(r[1]), "=r"(r[2]), "=r"(r[3]) : "r"(addr));
}
// vector reduction: g_agg[p..p+3] += {v0..v3}
__device__ __forceinline__ void red4(float* p, float v0, float v1, float v2, float v3) {
    asm volatile("red.global.add.v4.f32 [%0], {%1, %2, %3, %4};"
                 :: "l"(p), "f"(v0), "f"(v1), "f"(v2), "f"(v3) : "memory");
}
// cp.async 16B, L1-bypassing (.cg)
__device__ __forceinline__ void cpa16(uint32_t saddr, const void* gaddr) {
    asm volatile("cp.async.cg.shared.global [%0], [%1], 16;" :: "r"(saddr), "l"(gaddr));
}
#define CP_COMMIT() asm volatile("cp.async.commit_group;" ::: "memory")
#define CP_WAIT0()  asm volatile("cp.async.wait_group 0;" ::: "memory")
// f32x2 helpers (node kernel, validated R7)
__device__ __forceinline__ void ffma2(u64& d, u64 a, u64 b) {
    asm("fma.rn.f32x2 %0, %1, %2, %0;" : "+l"(d) : "l"(a), "l"(b));
}
__device__ __forceinline__ u64 pack2(float s) {
    u64 r; asm("mov.b64 %0, {%1, %1};" : "=l"(r) : "f"(s)); return r;
}
__device__ __forceinline__ void unpack2(u64 v, float& lo, float& hi) {
    asm("mov.b64 {%0, %1}, %2;" : "=f"(lo), "=f"(hi) : "l"(v));
}
__device__ __forceinline__ void ldg2x2(const float* p, u64& d0, u64& d1) {
    asm("ld.global.nc.v2.b64 {%0, %1}, [%2];" : "=l"(d0), "=l"(d1) : "l"(p));
}

// ===========================================================================
// Prep kernels
// ===========================================================================
__global__ void prep_features(const float* __restrict__ f) {
    int i = blockIdx.x * 256 + threadIdx.x;
    if (i < N_NODES * FDIM) gF[i] = __float2half_rn(f[i]);
}
__global__ void prep_wfrag(const float* __restrict__ W, int ksteps,
                           uint2* __restrict__ outF) {
    int i = blockIdx.x * 256 + threadIdx.x;
    if (i >= ksteps * 16 * 32) return;
    int lane = i & 31, fi = i >> 5;
    int kstep = fi >> 4, nfg = fi & 15;
    int n = nfg * 8 + (lane >> 2);
    __half v[2][2];
    #pragma unroll
    for (int j = 0; j < 2; j++)
        #pragma unroll
        for (int h = 0; h < 2; h++) {
            int k = kstep * 16 + j * 8 + (lane & 3) * 2 + h;
            v[j][h] = __float2half_rn(W[k * 128 + n]);
        }
    outF[i] = make_uint2(pack_h2(v[0][0], v[0][1]), pack_h2(v[1][0], v[1][1]));
}

// ===========================================================================
// Edge kernel: persistent, 296 CTAs x 256 threads, 2 CTAs/SM.
// Tile = 64 edges x 128 outs, 8 warps = 2M x 4N, fp16 mma.
// Cross-tile A double-buffer (cp.async), hoisted B prologues,
// shfl-paired red.v4 scatter.
// ===========================================================================
__global__ void __launch_bounds__(256, 2)
edge_mma_kernel(const int* __restrict__ rows,
                const int* __restrict__ cols,
                const float* __restrict__ bm1,
                const float* __restrict__ bm2)
{
    extern __shared__ char smem[];
    int*    sRowB = (int*)(smem + SM_ROW);     // [2][64]
    float*  sB1   = (float*)(smem + SM_B1);
    float*  sB2   = (float*)(smem + SM_B2);
    __half* sH    = (__half*)(smem + SM_H);

    const int tid  = threadIdx.x;
    const int lane = tid & 31;
    const int wid  = tid >> 5;
    const int wm   = wid & 1;
    const int wn   = wid >> 1;
    const uint32_t sb = smem_u32(smem);

    if (tid < 128) { sB1[tid] = __ldg(bm1 + tid); sB2[tid] = __ldg(bm2 + tid); }

    const int ge    = tid >> 2;
    const int gq    = tid & 3;
    const int ghalf = gq & 1;
    const int gseg  = gq >> 1;
    const uint32_t gDstOff = (uint32_t)((ge * LDA + ghalf * FDIM + gseg * 64) * 2);

    const int arow  = lane & 15;
    const int acolk = (lane >> 4) * 8;
    const int erow  = lane >> 2;
    const int ecol  = (lane & 3) * 2;
    const int odd   = lane & 1;

    const uint2* w1f = gW1f + wn * 4 * 32 + lane;
    const uint2* w2f = gW2f + wn * 4 * 32 + lane;

    const int stride = gridDim.x;
    int t = blockIdx.x;
    if (t >= N_TILES) return;

    // ---- prologue: gather tile t into buf 0, prefetch index for t+stride ----
    {
        int node = ghalf ? __ldg(cols + t * TILE_E + ge) : __ldg(rows + t * TILE_E + ge);
        if (tid < 16) cpa16(sb + SM_ROW + tid * 16, rows + t * TILE_E + tid * 4);
        const char* src = (const char*)(gF + (size_t)node * FDIM + gseg * 64);
        uint32_t dst = sb + SM_A + gDstOff;
        #pragma unroll
        for (int i = 0; i < 8; i++) cpa16(dst + i * 16, src + i * 16);
        CP_COMMIT();
    }
    int nodeAhead = 0;
    {
        int tn = t + stride;
        if (tn < N_TILES)
            nodeAhead = ghalf ? __ldg(cols + tn * TILE_E + ge) : __ldg(rows + tn * TILE_E + ge);
    }

    // preload GEMM1 ks=0 B fragments (lives across the loop)
    uint2 bf[2][4];
    #pragma unroll
    for (int nf = 0; nf < 4; nf++) bf[0][nf] = __ldg(w1f + nf * 32);

    CP_WAIT0();
    __syncthreads();

    int cur = 0;
    for (;;) {
        const int t_next = t + stride;
        const bool haveNext = (t_next < N_TILES);

        // ---- issue prefetch of tile t+1 into buf cur^1 ----
        if (haveNext) {
            if (tid < 16) cpa16(sb + SM_ROW + (cur ^ 1) * 256 + tid * 16,
                                rows + t_next * TILE_E + tid * 4);
            const char* src = (const char*)(gF + (size_t)nodeAhead * FDIM + gseg * 64);
            uint32_t dst = sb + SM_A + (cur ^ 1) * ABUF + gDstOff;
            #pragma unroll
            for (int i = 0; i < 8; i++) cpa16(dst + i * 16, src + i * 16);
            CP_COMMIT();
            int t2 = t_next + stride;
            if (t2 < N_TILES)
                nodeAhead = ghalf ? __ldg(cols + t2 * TILE_E + ge)
                                  : __ldg(rows + t2 * TILE_E + ge);
        }

        const uint32_t aBase = sb + SM_A + cur * ABUF;
        const int* sRow = sRowB + cur * 64;

        // ---- GEMM1: [64,256] @ W1[256,128], fp16, B double-buffered ----
        float4 acc[2][4];
        #pragma unroll
        for (int m = 0; m < 2; m++)
            #pragma unroll
            for (int nf = 0; nf < 4; nf++) acc[m][nf] = make_float4(0.f, 0.f, 0.f, 0.f);

        #pragma unroll 2
        for (int ks = 0; ks < 16; ks++) {
            const int c = ks & 1, nx = c ^ 1;
            uint32_t ah[2][4];
            #pragma unroll
            for (int m = 0; m < 2; m++) {
                uint32_t ab = aBase +
                    (uint32_t)(((wm * 32 + m * 16 + arow) * LDA + ks * 16 + acolk) * 2);
                ldmx4(ah[m], ab);
            }
            if (ks < 15) {
                #pragma unroll
                for (int nf = 0; nf < 4; nf++)
                    bf[nx][nf] = __ldg(w1f + ((ks + 1) * 16 + nf) * 32);
            }
            #pragma unroll
            for (int nf = 0; nf < 4; nf++)
                #pragma unroll
                for (int m = 0; m < 2; m++)
                    mma_f16(acc[m][nf], ah[m], bf[c][nf]);
        }

        // hoisted GEMM2 prologue: LDG latency hidden under epilogue-1 MUFUs
        #pragma unroll
        for (int nf = 0; nf < 4; nf++) bf[0][nf] = __ldg(w2f + nf * 32);

        // ---- epilogue 1: h = sigmoid(D1 + bm1) -> fp16 -> sH ----
        #pragma unroll
        for (int m = 0; m < 2; m++)
            #pragma unroll
            for (int nf = 0; nf < 4; nf++) {
                int r0 = wm * 32 + m * 16 + erow;
                int c  = wn * 32 + nf * 8 + ecol;
                float b0 = sB1[c], b1 = sB1[c + 1];
                *(uint32_t*)(sH + r0 * LDH + c) =
                    pack_h2(__float2half_rn(sigmoidf_(acc[m][nf].x + b0)),
                            __float2half_rn(sigmoidf_(acc[m][nf].y + b1)));
                *(uint32_t*)(sH + (r0 + 8) * LDH + c) =
                    pack_h2(__float2half_rn(sigmoidf_(acc[m][nf].z + b0)),
                            __float2half_rn(sigmoidf_(acc[m][nf].w + b1)));
            }
        __syncthreads();

        // ---- GEMM2: [64,128] @ W2[128,128], fp16 ----
        float4 acc2[2][4];
        #pragma unroll
        for (int m = 0; m < 2; m++)
            #pragma unroll
            for (int nf = 0; nf < 4; nf++) acc2[m][nf] = make_float4(0.f, 0.f, 0.f, 0.f);

        #pragma unroll 2
        for (int ks = 0; ks < 8; ks++) {
            const int c = ks & 1, nx = c ^ 1;
            uint32_t ah[2][4];
            #pragma unroll
            for (int m = 0; m < 2; m++) {
                uint32_t ab = sb + SM_H +
                    (uint32_t)(((wm * 32 + m * 16 + arow) * LDH + ks * 16 + acolk) * 2);
                ldmx4(ah[m], ab);
            }
            if (ks < 7) {
                #pragma unroll
                for (int nf = 0; nf < 4; nf++)
                    bf[nx][nf] = __ldg(w2f + ((ks + 1) * 16 + nf) * 32);
            }
            #pragma unroll
            for (int nf = 0; nf < 4; nf++)
                #pragma unroll
                for (int m = 0; m < 2; m++)
                    mma_f16(acc2[m][nf], ah[m], bf[c][nf]);
        }

        // hoisted next-tile GEMM1 prologue: hidden under the scatter epilogue
        #pragma unroll
        for (int nf = 0; nf < 4; nf++) bf[0][nf] = __ldg(w1f + nf * 32);

        // ---- epilogue 2: softsign + shfl-pair + red.v4 scatter ----
        #pragma unroll
        for (int m = 0; m < 2; m++) {
            int r0 = wm * 32 + m * 16 + erow;
            int n0 = sRow[r0];
            int n1 = sRow[r0 + 8];
            #pragma unroll
            for (int nf = 0; nf < 4; nf++) {
                int cb = wn * 32 + nf * 8 + ecol;
                float b0 = sB2[cb], b1 = sB2[cb + 1];
                float x = softsignf_(acc2[m][nf].x + b0);
                float y = softsignf_(acc2[m][nf].y + b1);
                float z = softsignf_(acc2[m][nf].z + b0);
                float w = softsignf_(acc2[m][nf].w + b1);
                // lane-pair exchange: even lane assembles 4 consecutive of row
                // r0; odd lane assembles 4 consecutive of row r0+8.
                float sa = odd ? x : z;
                float sc = odd ? y : w;
                float ra = __shfl_xor_sync(0xffffffffu, sa, 1);
                float rb = __shfl_xor_sync(0xffffffffu, sc, 1);
                if (odd) {
                    red4(g_agg + (size_t)n1 * FDIM + (cb - 2), ra, rb, z, w);
                } else {
                    red4(g_agg + (size_t)n0 * FDIM + cb, x, y, ra, rb);
                }
            }
        }

        if (!haveNext) break;
        CP_WAIT0();
        __syncthreads();
        t = t_next;
        cur ^= 1;
    }
}

// ===========================================================================
// Node kernel (R7 version, unchanged)
// ===========================================================================
#define TEN 64
#define NLDH 132
#define NLDN 388

__global__ void __launch_bounds__(256, 2)
node_kernel(const float* __restrict__ features,
            const float* __restrict__ time_emb,
            const float* __restrict__ Wf1,
            const float* __restrict__ bf1,
            const float* __restrict__ Wf2,
            const float* __restrict__ bf2,
            float* __restrict__ out)
{
    extern __shared__ float smemf[];
    float* sIn = smemf;

    const int tid = threadIdx.x;
    const int tx  = tid & 31;
    const int ty  = tid >> 5;
    const int n0  = blockIdx.x * TEN;

    for (int n = ty; n < TEN; n += 8) {
        int node = n0 + n;
        float4 a, g, t;
        if (node < N_NODES) {
            a = __ldg((const float4*)(features + (size_t)node * FDIM) + tx);
            g = *((const float4*)(g_agg + (size_t)node * FDIM) + tx);
            t = __ldg((const float4*)(time_emb + (size_t)node * FDIM) + tx);
        } else {
            a = g = t = make_float4(0.f, 0.f, 0.f, 0.f);
        }
        *(float4*)&sIn[n * NLDN + tx * 4] =
            make_float4(sigmoidf_(a.x), sigmoidf_(a.y), sigmoidf_(a.z), sigmoidf_(a.w));
        *(float4*)&sIn[n * NLDN + FDIM + tx * 4] =
            make_float4(sigmoidf_(g.x), sigmoidf_(g.y), sigmoidf_(g.z), sigmoidf_(g.w));
        *(float4*)&sIn[n * NLDN + 2 * FDIM + tx * 4] =
            make_float4(sigmoidf_(t.x), sigmoidf_(t.y), sigmoidf_(t.z), sigmoidf_(t.w));
    }
    __syncthreads();

    u64 acc[8][2];
    #pragma unroll
    for (int e = 0; e < 8; e++) { acc[e][0] = 0ull; acc[e][1] = 0ull; }

    const float* wBase = Wf1 + tx * 4;
    const float* aBase = sIn + (ty * 8) * NLDN;

    #pragma unroll 2
    for (int k = 0; k < 3 * FDIM; k += 4) {
        u64 w0a, w0b, w1a, w1b, w2a, w2b, w3a, w3b;
        ldg2x2(wBase + (k + 0) * FDIM, w0a, w0b);
        ldg2x2(wBase + (k + 1) * FDIM, w1a, w1b);
        ldg2x2(wBase + (k + 2) * FDIM, w2a, w2b);
        ldg2x2(wBase + (k + 3) * FDIM, w3a, w3b);
        #pragma unroll
        for (int e = 0; e < 8; e++) {
            float4 a = *(const float4*)(aBase + e * NLDN + k);
            u64 a0 = pack2(a.x), a1 = pack2(a.y), a2 = pack2(a.z), a3 = pack2(a.w);
            ffma2(acc[e][0], a0, w0a); ffma2(acc[e][1], a0, w0b);
            ffma2(acc[e][0], a1, w1a); ffma2(acc[e][1], a1, w1b);
            ffma2(acc[e][0], a2, w2a); ffma2(acc[e][1], a2, w2b);
            ffma2(acc[e][0], a3, w3a); ffma2(acc[e][1], a3, w3b);
        }
    }
    __syncthreads();

    float4 b1 = __ldg((const float4*)bf1 + tx);
    float* sHf = smemf;
    #pragma unroll
    for (int e = 0; e < 8; e++) {
        float x0, x1, x2, x3;
        unpack2(acc[e][0], x0, x1);
        unpack2(acc[e][1], x2, x3);
        float4 h;
        h.x = sigmoidf_(x0 + b1.x);
        h.y = sigmoidf_(x1 + b1.y);
        h.z = sigmoidf_(x2 + b1.z);
        h.w = sigmoidf_(x3 + b1.w);
        *(float4*)&sHf[(ty * 8 + e) * NLDH + tx * 4] = h;
    }
    __syncthreads();

    u64 acc2[8][2];
    #pragma unroll
    for (int e = 0; e < 8; e++) { acc2[e][0] = 0ull; acc2[e][1] = 0ull; }

    const float* w2Base = Wf2 + tx * 4;
    const float* hBase  = sHf + (ty * 8) * NLDH;

    #pragma unroll 2
    for (int k = 0; k < FDIM; k += 4) {
        u64 w0a, w0b, w1a, w1b, w2a, w2b, w3a, w3b;
        ldg2x2(w2Base + (k + 0) * FDIM, w0a, w0b);
        ldg2x2(w2Base + (k + 1) * FDIM, w1a, w1b);
        ldg2x2(w2Base + (k + 2) * FDIM, w2a, w2b);
        ldg2x2(w2Base + (k + 3) * FDIM, w3a, w3b);
        #pragma unroll
        for (int e = 0; e < 8; e++) {
            float4 a = *(const float4*)(hBase + e * NLDH + k);
            u64 a0 = pack2(a.x), a1 = pack2(a.y), a2 = pack2(a.z), a3 = pack2(a.w);
            ffma2(acc2[e][0], a0, w0a); ffma2(acc2[e][1], a0, w0b);
            ffma2(acc2[e][0], a1, w1a); ffma2(acc2[e][1], a1, w1b);
            ffma2(acc2[e][0], a2, w2a); ffma2(acc2[e][1], a2, w2b);
            ffma2(acc2[e][0], a3, w3a); ffma2(acc2[e][1], a3, w3b);
        }
    }

    float4 b2 = __ldg((const float4*)bf2 + tx);
    #pragma unroll
    for (int e = 0; e < 8; e++) {
        int node = n0 + ty * 8 + e;
        if (node < N_NODES) {
            float x0, x1, x2, x3;
            unpack2(acc2[e][0], x0, x1);
            unpack2(acc2[e][1], x2, x3);
            float4 o;
            o.x = softsignf_(x0 + b2.x);
            o.y = softsignf_(x1 + b2.y);
            o.z = softsignf_(x2 + b2.z);
            o.w = softsignf_(x3 + b2.w);
            *(float4*)(out + (size_t)node * FDIM + tx * 4) = o;
        }
    }
}

// ===========================================================================
extern "C" void kernel_launch(void* const* d_in, const int* in_sizes, int n_in,
                              void* d_out, int out_size)
{
    const float* features = (const float*)d_in[0];
    const int*   rows     = (const int*)  d_in[1];
    const int*   cols     = (const int*)  d_in[2];
    const float* time_emb = (const float*)d_in[3];
    const float* Wm1      = (const float*)d_in[4];
    const float* bm1      = (const float*)d_in[5];
    const float* Wm2      = (const float*)d_in[6];
    const float* bm2      = (const float*)d_in[7];
    const float* Wf1      = (const float*)d_in[8];
    const float* bf1      = (const float*)d_in[9];
    const float* Wf2      = (const float*)d_in[10];
    const float* bf2      = (const float*)d_in[11];
    float* out = (float*)d_out;

    const int node_smem = TEN * NLDN * sizeof(float);
    cudaFuncSetAttribute(edge_mma_kernel, cudaFuncAttributeMaxDynamicSharedMemorySize, SM_TOTAL);
    cudaFuncSetAttribute(node_kernel,     cudaFuncAttributeMaxDynamicSharedMemorySize, node_smem);

    void* aggp = nullptr;
    cudaGetSymbolAddress(&aggp, g_agg);
    cudaMemsetAsync(aggp, 0, (size_t)N_NODES * FDIM * sizeof(float));

    uint2 *w1f, *w2f;
    cudaGetSymbolAddress((void**)&w1f, gW1f);
    cudaGetSymbolAddress((void**)&w2f, gW2f);

    prep_features<<<(N_NODES * FDIM + 255) / 256, 256>>>(features);
    prep_wfrag<<<32, 256>>>(Wm1, 16, w1f);
    prep_wfrag<<<16, 256>>>(Wm2,  8, w2f);

    edge_mma_kernel<<<296, 256, SM_TOTAL>>>(rows, cols, bm1, bm2);

    node_kernel<<<(N_NODES + TEN - 1) / TEN, 256, node_smem>>>(features, time_emb,
                                                               Wf1, bf1, Wf2, bf2, out);
}

// round 16
// speedup vs baseline: 1.1789x; 1.1789x over previous
#include <cuda_runtime.h>
#include <cuda_fp16.h>
#include <math.h>
#include <stdint.h>

#define N_NODES 10000
#define N_EDGES 640000
#define FDIM    128
#define TILE_E  64
#define N_TILES (N_EDGES / TILE_E)   // 10000

#define LDA 264   // smem stride (fp16) for A tile: 256 + 8
#define LDH 136   // smem stride (fp16) for h tile: 128 + 8
#define ABUF (TILE_E * LDA * 2)      // 33792 bytes per A buffer

// ---- smem map (bytes), per CTA ~84.5KB -> 2 CTAs/SM ----
#define SM_ROW   0                    // 2 x 64 ints (ping-pong)
#define SM_B1    512
#define SM_B2    1024
#define SM_A     1536                 // 2 x ABUF
#define SM_H     (SM_A + 2 * ABUF)    // 69120
#define SM_TOTAL (SM_H + TILE_E * LDH * 2)   // 86528

// ===========================================================================
__device__ float  g_agg[N_NODES * FDIM];
__device__ __half gF[N_NODES * FDIM];
__device__ uint2 gW1f[256 * 32];
__device__ uint2 gW2f[128 * 32];

typedef unsigned long long u64;

__device__ __forceinline__ float sigmoidf_(float x) { return 1.0f / (1.0f + __expf(-x)); }
__device__ __forceinline__ float softsignf_(float x) { return x / (1.0f + fabsf(x)); }

__device__ __forceinline__ uint32_t smem_u32(const void* p) {
    uint32_t a;
    asm("{ .reg .u64 t; cvta.to.shared.u64 t, %1; cvt.u32.u64 %0, t; }" : "=r"(a) : "l"(p));
    return a;
}
__device__ __forceinline__ uint32_t pack_h2(__half lo, __half hi) {
    __half2 v; v.x = lo; v.y = hi;
    return *(uint32_t*)&v;
}
// fast fp16x2 sigmoid: inputs are 0.5*(acc+bias); sig = 0.5*tanh(.)+0.5
__device__ __forceinline__ uint32_t sig2_h2(float x0, float x1) {
    __half2 t = __floats2half2_rn(x0, x1);
    uint32_t r;
    asm("tanh.approx.f16x2 %0, %1;" : "=r"(r) : "r"(*(uint32_t*)&t));
    __half2 th = *(__half2*)&r;
    __half2 h = __hfma2(th, __float2half2_rn(0.5f), __float2half2_rn(0.5f));
    return *(uint32_t*)&h;
}
__device__ __forceinline__ void mma_f16(float4& d, const uint32_t a[4], uint2 b) {
    asm volatile(
        "mma.sync.aligned.m16n8k16.row.col.f32.f16.f16.f32 "
        "{%0,%1,%2,%3}, {%4,%5,%6,%7}, {%8,%9}, {%0,%1,%2,%3};"
        : "+f"(d.x), "+f"(d.y), "+f"(d.z), "+f"(d.w)
        : "r"(a[0]), "r"(a[1]), "r"(a[2]), "r"(a[3]), "r"(b.x), "r"(b.y));
}
__device__ __forceinline__ void ldmx4(uint32_t r[4], uint32_t addr) {
    asm volatile("ldmatrix.sync.aligned.m8n8.x4.shared.b16 {%0,%1,%2,%3}, [%4];"
                 : "=r"(r[0]), "=r"(r[1]), "=r"(r[2]), "=r"(r[3]) : "r"(addr));
}
__device__ __forceinline__ void red2(float* p, float v0, float v1) {
    asm volatile("red.global.add.v2.f32 [%0], {%1, %2};" :: "l"(p), "f"(v0), "f"(v1) : "memory");
}
// cp.async 16B, L1-bypassing (.cg)
__device__ __forceinline__ void cpa16(uint32_t saddr, const void* gaddr) {
    asm volatile("cp.async.cg.shared.global [%0], [%1], 16;" :: "r"(saddr), "l"(gaddr));
}
#define CP_COMMIT() asm volatile("cp.async.commit_group;" ::: "memory")
#define CP_WAIT0()  asm volatile("cp.async.wait_group 0;" ::: "memory")
// f32x2 helpers (node kernel, validated R7)
__device__ __forceinline__ void ffma2(u64& d, u64 a, u64 b) {
    asm("fma.rn.f32x2 %0, %1, %2, %0;" : "+l"(d) : "l"(a), "l"(b));
}
__device__ __forceinline__ u64 pack2(float s) {
    u64 r; asm("mov.b64 %0, {%1, %1};" : "=l"(r) : "f"(s)); return r;
}
__device__ __forceinline__ void unpack2(u64 v, float& lo, float& hi) {
    asm("mov.b64 {%0, %1}, %2;" : "=f"(lo), "=f"(hi) : "l"(v));
}
__device__ __forceinline__ void ldg2x2(const float* p, u64& d0, u64& d1) {
    asm("ld.global.nc.v2.b64 {%0, %1}, [%2];" : "=l"(d0), "=l"(d1) : "l"(p));
}

// ===========================================================================
// Prep kernels
// ===========================================================================
__global__ void prep_features(const float* __restrict__ f) {
    int i = blockIdx.x * 256 + threadIdx.x;
    if (i < N_NODES * FDIM) gF[i] = __float2half_rn(f[i]);
}
__global__ void prep_wfrag(const float* __restrict__ W, int ksteps,
                           uint2* __restrict__ outF) {
    int i = blockIdx.x * 256 + threadIdx.x;
    if (i >= ksteps * 16 * 32) return;
    int lane = i & 31, fi = i >> 5;
    int kstep = fi >> 4, nfg = fi & 15;
    int n = nfg * 8 + (lane >> 2);
    __half v[2][2];
    #pragma unroll
    for (int j = 0; j < 2; j++)
        #pragma unroll
        for (int h = 0; h < 2; h++) {
            int k = kstep * 16 + j * 8 + (lane & 3) * 2 + h;
            v[j][h] = __float2half_rn(W[k * 128 + n]);
        }
    outF[i] = make_uint2(pack_h2(v[0][0], v[0][1]), pack_h2(v[1][0], v[1][1]));
}

// ===========================================================================
// Edge kernel: persistent, 296 CTAs x 256 threads, 2 CTAs/SM.
// Tile = 64 edges x 128 outs, 8 warps = 2M x 4N, fp16 mma.
// Cross-tile A double-buffer (cp.async), tanh.f16x2 sigmoid epilogue,
// registered biases, red2 scatter.
// ===========================================================================
__global__ void __launch_bounds__(256, 2)
edge_mma_kernel(const int* __restrict__ rows,
                const int* __restrict__ cols,
                const float* __restrict__ bm1,
                const float* __restrict__ bm2)
{
    extern __shared__ char smem[];
    int*    sRowB = (int*)(smem + SM_ROW);     // [2][64]
    float*  sB1   = (float*)(smem + SM_B1);
    float*  sB2   = (float*)(smem + SM_B2);
    __half* sH    = (__half*)(smem + SM_H);

    const int tid  = threadIdx.x;
    const int lane = tid & 31;
    const int wid  = tid >> 5;
    const int wm   = wid & 1;
    const int wn   = wid >> 1;
    const uint32_t sb = smem_u32(smem);

    if (tid < 128) { sB1[tid] = __ldg(bm1 + tid); sB2[tid] = __ldg(bm2 + tid); }

    const int ge    = tid >> 2;
    const int gq    = tid & 3;
    const int ghalf = gq & 1;
    const int gseg  = gq >> 1;
    const uint32_t gDstOff = (uint32_t)((ge * LDA + ghalf * FDIM + gseg * 64) * 2);

    const int arow  = lane & 15;
    const int acolk = (lane >> 4) * 8;
    const int erow  = lane >> 2;
    const int ecol  = (lane & 3) * 2;

    const uint2* w1f = gW1f + wn * 4 * 32 + lane;
    const uint2* w2f = gW2f + wn * 4 * 32 + lane;

    const int stride = gridDim.x;
    int t = blockIdx.x;
    if (t >= N_TILES) return;

    // ---- prologue: gather tile t into buf 0 ----
    {
        int node = ghalf ? __ldg(cols + t * TILE_E + ge) : __ldg(rows + t * TILE_E + ge);
        if (tid < 16) cpa16(sb + SM_ROW + tid * 16, rows + t * TILE_E + tid * 4);
        const char* src = (const char*)(gF + (size_t)node * FDIM + gseg * 64);
        uint32_t dst = sb + SM_A + gDstOff;
        #pragma unroll
        for (int i = 0; i < 8; i++) cpa16(dst + i * 16, src + i * 16);
        CP_COMMIT();
    }
    int nodeAhead = 0;
    {
        int tn = t + stride;
        if (tn < N_TILES)
            nodeAhead = ghalf ? __ldg(cols + tn * TILE_E + ge) : __ldg(rows + tn * TILE_E + ge);
    }
    CP_WAIT0();
    __syncthreads();

    // ---- hoist per-lane biases into registers (tile-invariant) ----
    float b1h0[4], b1h1[4], b20[4], b21[4];
    #pragma unroll
    for (int nf = 0; nf < 4; nf++) {
        int c = wn * 32 + nf * 8 + ecol;
        b1h0[nf] = 0.5f * sB1[c];
        b1h1[nf] = 0.5f * sB1[c + 1];
        b20[nf]  = sB2[c];
        b21[nf]  = sB2[c + 1];
    }

    int cur = 0;
    for (;;) {
        const int t_next = t + stride;
        const bool haveNext = (t_next < N_TILES);

        // ---- issue prefetch of tile t+1 into buf cur^1 ----
        if (haveNext) {
            if (tid < 16) cpa16(sb + SM_ROW + (cur ^ 1) * 256 + tid * 16,
                                rows + t_next * TILE_E + tid * 4);
            const char* src = (const char*)(gF + (size_t)nodeAhead * FDIM + gseg * 64);
            uint32_t dst = sb + SM_A + (cur ^ 1) * ABUF + gDstOff;
            #pragma unroll
            for (int i = 0; i < 8; i++) cpa16(dst + i * 16, src + i * 16);
            CP_COMMIT();
            int t2 = t_next + stride;
            if (t2 < N_TILES)
                nodeAhead = ghalf ? __ldg(cols + t2 * TILE_E + ge)
                                  : __ldg(rows + t2 * TILE_E + ge);
        }

        const uint32_t aBase = sb + SM_A + cur * ABUF;
        const int* sRow = sRowB + cur * 64;

        // ---- GEMM1: [64,256] @ W1[256,128], fp16, B double-buffered ----
        float4 acc[2][4];
        #pragma unroll
        for (int m = 0; m < 2; m++)
            #pragma unroll
            for (int nf = 0; nf < 4; nf++) acc[m][nf] = make_float4(0.f, 0.f, 0.f, 0.f);

        uint2 bf[2][4];
        #pragma unroll
        for (int nf = 0; nf < 4; nf++) bf[0][nf] = __ldg(w1f + nf * 32);

        #pragma unroll 2
        for (int ks = 0; ks < 16; ks++) {
            const int c = ks & 1, nx = c ^ 1;
            uint32_t ah[2][4];
            #pragma unroll
            for (int m = 0; m < 2; m++) {
                uint32_t ab = aBase +
                    (uint32_t)(((wm * 32 + m * 16 + arow) * LDA + ks * 16 + acolk) * 2);
                ldmx4(ah[m], ab);
            }
            if (ks < 15) {
                #pragma unroll
                for (int nf = 0; nf < 4; nf++)
                    bf[nx][nf] = __ldg(w1f + ((ks + 1) * 16 + nf) * 32);
            }
            #pragma unroll
            for (int nf = 0; nf < 4; nf++)
                #pragma unroll
                for (int m = 0; m < 2; m++)
                    mma_f16(acc[m][nf], ah[m], bf[c][nf]);
        }

        // ---- epilogue 1: h = sigmoid(D1 + bm1) via tanh.f16x2 -> sH ----
        #pragma unroll
        for (int m = 0; m < 2; m++)
            #pragma unroll
            for (int nf = 0; nf < 4; nf++) {
                int r0 = wm * 32 + m * 16 + erow;
                int c  = wn * 32 + nf * 8 + ecol;
                *(uint32_t*)(sH + r0 * LDH + c) =
                    sig2_h2(fmaf(acc[m][nf].x, 0.5f, b1h0[nf]),
                            fmaf(acc[m][nf].y, 0.5f, b1h1[nf]));
                *(uint32_t*)(sH + (r0 + 8) * LDH + c) =
                    sig2_h2(fmaf(acc[m][nf].z, 0.5f, b1h0[nf]),
                            fmaf(acc[m][nf].w, 0.5f, b1h1[nf]));
            }
        __syncthreads();

        // ---- GEMM2: [64,128] @ W2[128,128], fp16 ----
        float4 acc2[2][4];
        #pragma unroll
        for (int m = 0; m < 2; m++)
            #pragma unroll
            for (int nf = 0; nf < 4; nf++) acc2[m][nf] = make_float4(0.f, 0.f, 0.f, 0.f);

        #pragma unroll
        for (int nf = 0; nf < 4; nf++) bf[0][nf] = __ldg(w2f + nf * 32);

        #pragma unroll 2
        for (int ks = 0; ks < 8; ks++) {
            const int c = ks & 1, nx = c ^ 1;
            uint32_t ah[2][4];
            #pragma unroll
            for (int m = 0; m < 2; m++) {
                uint32_t ab = sb + SM_H +
                    (uint32_t)(((wm * 32 + m * 16 + arow) * LDH + ks * 16 + acolk) * 2);
                ldmx4(ah[m], ab);
            }
            if (ks < 7) {
                #pragma unroll
                for (int nf = 0; nf < 4; nf++)
                    bf[nx][nf] = __ldg(w2f + ((ks + 1) * 16 + nf) * 32);
            }
            #pragma unroll
            for (int nf = 0; nf < 4; nf++)
                #pragma unroll
                for (int m = 0; m < 2; m++)
                    mma_f16(acc2[m][nf], ah[m], bf[c][nf]);
        }

        // ---- epilogue 2: softsign + red2 scatter into g_agg ----
        #pragma unroll
        for (int m = 0; m < 2; m++) {
            int r0 = wm * 32 + m * 16 + erow;
            int n0 = sRow[r0];
            int n1 = sRow[r0 + 8];
            #pragma unroll
            for (int nf = 0; nf < 4; nf++) {
                int cb = wn * 32 + nf * 8 + ecol;
                red2(g_agg + (size_t)n0 * FDIM + cb,
                     softsignf_(acc2[m][nf].x + b20[nf]),
                     softsignf_(acc2[m][nf].y + b21[nf]));
                red2(g_agg + (size_t)n1 * FDIM + cb,
                     softsignf_(acc2[m][nf].z + b20[nf]),
                     softsignf_(acc2[m][nf].w + b21[nf]));
            }
        }

        if (!haveNext) break;
        CP_WAIT0();
        __syncthreads();
        t = t_next;
        cur ^= 1;
    }
}

// ===========================================================================
// Node kernel (R7 version, unchanged)
// ===========================================================================
#define TEN 64
#define NLDH 132
#define NLDN 388

__global__ void __launch_bounds__(256, 2)
node_kernel(const float* __restrict__ features,
            const float* __restrict__ time_emb,
            const float* __restrict__ Wf1,
            const float* __restrict__ bf1,
            const float* __restrict__ Wf2,
            const float* __restrict__ bf2,
            float* __restrict__ out)
{
    extern __shared__ float smemf[];
    float* sIn = smemf;

    const int tid = threadIdx.x;
    const int tx  = tid & 31;
    const int ty  = tid >> 5;
    const int n0  = blockIdx.x * TEN;

    for (int n = ty; n < TEN; n += 8) {
        int node = n0 + n;
        float4 a, g, t;
        if (node < N_NODES) {
            a = __ldg((const float4*)(features + (size_t)node * FDIM) + tx);
            g = *((const float4*)(g_agg + (size_t)node * FDIM) + tx);
            t = __ldg((const float4*)(time_emb + (size_t)node * FDIM) + tx);
        } else {
            a = g = t = make_float4(0.f, 0.f, 0.f, 0.f);
        }
        *(float4*)&sIn[n * NLDN + tx * 4] =
            make_float4(sigmoidf_(a.x), sigmoidf_(a.y), sigmoidf_(a.z), sigmoidf_(a.w));
        *(float4*)&sIn[n * NLDN + FDIM + tx * 4] =
            make_float4(sigmoidf_(g.x), sigmoidf_(g.y), sigmoidf_(g.z), sigmoidf_(g.w));
        *(float4*)&sIn[n * NLDN + 2 * FDIM + tx * 4] =
            make_float4(sigmoidf_(t.x), sigmoidf_(t.y), sigmoidf_(t.z), sigmoidf_(t.w));
    }
    __syncthreads();

    u64 acc[8][2];
    #pragma unroll
    for (int e = 0; e < 8; e++) { acc[e][0] = 0ull; acc[e][1] = 0ull; }

    const float* wBase = Wf1 + tx * 4;
    const float* aBase = sIn + (ty * 8) * NLDN;

    #pragma unroll 2
    for (int k = 0; k < 3 * FDIM; k += 4) {
        u64 w0a, w0b, w1a, w1b, w2a, w2b, w3a, w3b;
        ldg2x2(wBase + (k + 0) * FDIM, w0a, w0b);
        ldg2x2(wBase + (k + 1) * FDIM, w1a, w1b);
        ldg2x2(wBase + (k + 2) * FDIM, w2a, w2b);
        ldg2x2(wBase + (k + 3) * FDIM, w3a, w3b);
        #pragma unroll
        for (int e = 0; e < 8; e++) {
            float4 a = *(const float4*)(aBase + e * NLDN + k);
            u64 a0 = pack2(a.x), a1 = pack2(a.y), a2 = pack2(a.z), a3 = pack2(a.w);
            ffma2(acc[e][0], a0, w0a); ffma2(acc[e][1], a0, w0b);
            ffma2(acc[e][0], a1, w1a); ffma2(acc[e][1], a1, w1b);
            ffma2(acc[e][0], a2, w2a); ffma2(acc[e][1], a2, w2b);
            ffma2(acc[e][0], a3, w3a); ffma2(acc[e][1], a3, w3b);
        }
    }
    __syncthreads();

    float4 b1 = __ldg((const float4*)bf1 + tx);
    float* sHf = smemf;
    #pragma unroll
    for (int e = 0; e < 8; e++) {
        float x0, x1, x2, x3;
        unpack2(acc[e][0], x0, x1);
        unpack2(acc[e][1], x2, x3);
        float4 h;
        h.x = sigmoidf_(x0 + b1.x);
        h.y = sigmoidf_(x1 + b1.y);
        h.z = sigmoidf_(x2 + b1.z);
        h.w = sigmoidf_(x3 + b1.w);
        *(float4*)&sHf[(ty * 8 + e) * NLDH + tx * 4] = h;
    }
    __syncthreads();

    u64 acc2[8][2];
    #pragma unroll
    for (int e = 0; e < 8; e++) { acc2[e][0] = 0ull; acc2[e][1] = 0ull; }

    const float* w2Base = Wf2 + tx * 4;
    const float* hBase  = sHf + (ty * 8) * NLDH;

    #pragma unroll 2
    for (int k = 0; k < FDIM; k += 4) {
        u64 w0a, w0b, w1a, w1b, w2a, w2b, w3a, w3b;
        ldg2x2(w2Base + (k + 0) * FDIM, w0a, w0b);
        ldg2x2(w2Base + (k + 1) * FDIM, w1a, w1b);
        ldg2x2(w2Base + (k + 2) * FDIM, w2a, w2b);
        ldg2x2(w2Base + (k + 3) * FDIM, w3a, w3b);
        #pragma unroll
        for (int e = 0; e < 8; e++) {
            float4 a = *(const float4*)(hBase + e * NLDH + k);
            u64 a0 = pack2(a.x), a1 = pack2(a.y), a2 = pack2(a.z), a3 = pack2(a.w);
            ffma2(acc2[e][0], a0, w0a); ffma2(acc2[e][1], a0, w0b);
            ffma2(acc2[e][0], a1, w1a); ffma2(acc2[e][1], a1, w1b);
            ffma2(acc2[e][0], a2, w2a); ffma2(acc2[e][1], a2, w2b);
            ffma2(acc2[e][0], a3, w3a); ffma2(acc2[e][1], a3, w3b);
        }
    }

    float4 b2 = __ldg((const float4*)bf2 + tx);
    #pragma unroll
    for (int e = 0; e < 8; e++) {
        int node = n0 + ty * 8 + e;
        if (node < N_NODES) {
            float x0, x1, x2, x3;
            unpack2(acc2[e][0], x0, x1);
            unpack2(acc2[e][1], x2, x3);
            float4 o;
            o.x = softsignf_(x0 + b2.x);
            o.y = softsignf_(x1 + b2.y);
            o.z = softsignf_(x2 + b2.z);
            o.w = softsignf_(x3 + b2.w);
            *(float4*)(out + (size_t)node * FDIM + tx * 4) = o;
        }
    }
}

// ===========================================================================
extern "C" void kernel_launch(void* const* d_in, const int* in_sizes, int n_in,
                              void* d_out, int out_size)
{
    const float* features = (const float*)d_in[0];
    const int*   rows     = (const int*)  d_in[1];
    const int*   cols     = (const int*)  d_in[2];
    const float* time_emb = (const float*)d_in[3];
    const float* Wm1      = (const float*)d_in[4];
    const float* bm1      = (const float*)d_in[5];
    const float* Wm2      = (const float*)d_in[6];
    const float* bm2      = (const float*)d_in[7];
    const float* Wf1      = (const float*)d_in[8];
    const float* bf1      = (const float*)d_in[9];
    const float* Wf2      = (const float*)d_in[10];
    const float* bf2      = (const float*)d_in[11];
    float* out = (float*)d_out;

    const int node_smem = TEN * NLDN * sizeof(float);
    cudaFuncSetAttribute(edge_mma_kernel, cudaFuncAttributeMaxDynamicSharedMemorySize, SM_TOTAL);
    cudaFuncSetAttribute(node_kernel,     cudaFuncAttributeMaxDynamicSharedMemorySize, node_smem);

    void* aggp = nullptr;
    cudaGetSymbolAddress(&aggp, g_agg);
    cudaMemsetAsync(aggp, 0, (size_t)N_NODES * FDIM * sizeof(float));

    uint2 *w1f, *w2f;
    cudaGetSymbolAddress((void**)&w1f, gW1f);
    cudaGetSymbolAddress((void**)&w2f, gW2f);

    prep_features<<<(N_NODES * FDIM + 255) / 256, 256>>>(features);
    prep_wfrag<<<32, 256>>>(Wm1, 16, w1f);
    prep_wfrag<<<16, 256>>>(Wm2,  8, w2f);

    edge_mma_kernel<<<296, 256, SM_TOTAL>>>(rows, cols, bm1, bm2);

    node_kernel<<<(N_NODES + TEN - 1) / TEN, 256, node_smem>>>(features, time_emb,
                                                               Wf1, bf1, Wf2, bf2, out);
}

// round 17
// speedup vs baseline: 1.2093x; 1.0258x over previous
#include <cuda_runtime.h>
#include <cuda_fp16.h>
#include <math.h>
#include <stdint.h>

#define N_NODES 10000
#define N_EDGES 640000
#define FDIM    128
#define TILE_E  64
#define N_TILES (N_EDGES / TILE_E)   // 10000

#define LDA 264   // smem stride (fp16) for A tile: 256 + 8
#define LDH 136   // smem stride (fp16) for h tile: 128 + 8
#define ABUF (TILE_E * LDA * 2)      // 33792 bytes per A buffer

// ---- smem map (bytes), per CTA ~84.5KB -> 2 CTAs/SM ----
#define SM_ROW   0                    // 2 x 64 ints (ping-pong)
#define SM_B1    512
#define SM_B2    1024
#define SM_A     1536                 // 2 x ABUF
#define SM_H     (SM_A + 2 * ABUF)    // 69120
#define SM_TOTAL (SM_H + TILE_E * LDH * 2)   // 86528

// ===========================================================================
__device__ float  g_agg[N_NODES * FDIM];
__device__ __half gF[N_NODES * FDIM];
// pair-packed weight fragments: one uint4 = two adjacent n-fragments (nf even|odd)
// index: [(kstep*8 + nfpair)*32 + lane]
__device__ uint4 gW1q[16 * 8 * 32];
__device__ uint4 gW2q[8 * 8 * 32];

typedef unsigned long long u64;

__device__ __forceinline__ float sigmoidf_(float x) { return 1.0f / (1.0f + __expf(-x)); }
__device__ __forceinline__ float softsignf_(float x) { return x / (1.0f + fabsf(x)); }

__device__ __forceinline__ uint32_t smem_u32(const void* p) {
    uint32_t a;
    asm("{ .reg .u64 t; cvta.to.shared.u64 t, %1; cvt.u32.u64 %0, t; }" : "=r"(a) : "l"(p));
    return a;
}
__device__ __forceinline__ uint32_t pack_h2(__half lo, __half hi) {
    __half2 v; v.x = lo; v.y = hi;
    return *(uint32_t*)&v;
}
// fast fp16x2 sigmoid: inputs are 0.5*(acc)+0.5*bias; sig = 0.5*tanh(.)+0.5
__device__ __forceinline__ uint32_t sig2_h2(float x0, float x1) {
    __half2 t = __floats2half2_rn(x0, x1);
    uint32_t r;
    asm("tanh.approx.f16x2 %0, %1;" : "=r"(r) : "r"(*(uint32_t*)&t));
    __half2 th = *(__half2*)&r;
    __half2 h = __hfma2(th, __float2half2_rn(0.5f), __float2half2_rn(0.5f));
    return *(uint32_t*)&h;
}
__device__ __forceinline__ void mma_f16(float4& d, const uint32_t a[4], uint2 b) {
    asm volatile(
        "mma.sync.aligned.m16n8k16.row.col.f32.f16.f16.f32 "
        "{%0,%1,%2,%3}, {%4,%5,%6,%7}, {%8,%9}, {%0,%1,%2,%3};"
        : "+f"(d.x), "+f"(d.y), "+f"(d.z), "+f"(d.w)
        : "r"(a[0]), "r"(a[1]), "r"(a[2]), "r"(a[3]), "r"(b.x), "r"(b.y));
}
__device__ __forceinline__ void ldmx4(uint32_t r[4], uint32_t addr) {
    asm volatile("ldmatrix.sync.aligned.m8n8.x4.shared.b16 {%0,%1,%2,%3}, [%4];"
                 : "=r"(r[0]), "=r"(r[1]), "=r"(r[2]), "=r"(r[3]) : "r"(addr));
}
__device__ __forceinline__ void red2(float* p, float v0, float v1) {
    asm volatile("red.global.add.v2.f32 [%0], {%1, %2};" :: "l"(p), "f"(v0), "f"(v1) : "memory");
}
__device__ __forceinline__ void cpa16(uint32_t saddr, const void* gaddr) {
    asm volatile("cp.async.cg.shared.global [%0], [%1], 16;" :: "r"(saddr), "l"(gaddr));
}
#define CP_COMMIT() asm volatile("cp.async.commit_group;" ::: "memory")
#define CP_WAIT0()  asm volatile("cp.async.wait_group 0;" ::: "memory")
#define BAR_SYNC(id) asm volatile("bar.sync %0, 128;" :: "r"(id) : "memory")
// f32x2 helpers (node kernel, validated R7)
__device__ __forceinline__ void ffma2(u64& d, u64 a, u64 b) {
    asm("fma.rn.f32x2 %0, %1, %2, %0;" : "+l"(d) : "l"(a), "l"(b));
}
__device__ __forceinline__ u64 pack2(float s) {
    u64 r; asm("mov.b64 %0, {%1, %1};" : "=l"(r) : "f"(s)); return r;
}
__device__ __forceinline__ void unpack2(u64 v, float& lo, float& hi) {
    asm("mov.b64 {%0, %1}, %2;" : "=f"(lo), "=f"(hi) : "l"(v));
}
__device__ __forceinline__ void ldg2x2(const float* p, u64& d0, u64& d1) {
    asm("ld.global.nc.v2.b64 {%0, %1}, [%2];" : "=l"(d0), "=l"(d1) : "l"(p));
}

// ===========================================================================
// Prep kernels
// ===========================================================================
__global__ void prep_features(const float* __restrict__ f) {
    int i = blockIdx.x * 256 + threadIdx.x;
    if (i < N_NODES * FDIM) gF[i] = __float2half_rn(f[i]);
}
// Build pair-packed B fragments for W [K x 128] row-major.
// thread computes one (kstep, nfg, lane) uint2 fragment, writes it into the
// even/odd half of the uint4 pair entry.
__global__ void prep_wfrag(const float* __restrict__ W, int ksteps,
                           uint4* __restrict__ outQ) {
    int i = blockIdx.x * 256 + threadIdx.x;
    if (i >= ksteps * 16 * 32) return;
    int lane = i & 31, fi = i >> 5;
    int kstep = fi >> 4, nfg = fi & 15;
    int n = nfg * 8 + (lane >> 2);
    __half v[2][2];
    #pragma unroll
    for (int j = 0; j < 2; j++)
        #pragma unroll
        for (int h = 0; h < 2; h++) {
            int k = kstep * 16 + j * 8 + (lane & 3) * 2 + h;
            v[j][h] = __float2half_rn(W[k * 128 + n]);
        }
    uint2 frag = make_uint2(pack_h2(v[0][0], v[0][1]), pack_h2(v[1][0], v[1][1]));
    ((uint2*)outQ)[(size_t)(((kstep * 8 + (nfg >> 1)) * 32 + lane) * 2 + (nfg & 1))] = frag;
}

// ===========================================================================
// Edge kernel: persistent, 296 CTAs x 256 threads, 2 CTAs/SM.
// Tile = 64 edges x 128 outs, 8 warps = 2M x 4N, fp16 mma.
// Cross-tile A double-buffer (cp.async), tanh.f16x2 epilogue, paired uint4
// weight loads (half the weight-LDG count), named-barrier epi1 sync.
// ===========================================================================
__global__ void __launch_bounds__(256, 2)
edge_mma_kernel(const int* __restrict__ rows,
                const int* __restrict__ cols,
                const float* __restrict__ bm1,
                const float* __restrict__ bm2)
{
    extern __shared__ char smem[];
    int*    sRowB = (int*)(smem + SM_ROW);     // [2][64]
    float*  sB1   = (float*)(smem + SM_B1);
    float*  sB2   = (float*)(smem + SM_B2);
    __half* sH    = (__half*)(smem + SM_H);

    const int tid  = threadIdx.x;
    const int lane = tid & 31;
    const int wid  = tid >> 5;
    const int wm   = wid & 1;
    const int wn   = wid >> 1;
    const uint32_t sb = smem_u32(smem);

    if (tid < 128) { sB1[tid] = __ldg(bm1 + tid); sB2[tid] = __ldg(bm2 + tid); }

    const int ge    = tid >> 2;
    const int gq    = tid & 3;
    const int ghalf = gq & 1;
    const int gseg  = gq >> 1;
    const uint32_t gDstOff = (uint32_t)((ge * LDA + ghalf * FDIM + gseg * 64) * 2);

    const int arow  = lane & 15;
    const int acolk = (lane >> 4) * 8;
    const int erow  = lane >> 2;
    const int ecol  = (lane & 3) * 2;

    // per-warp base pointers: pair entries (wn*2, wn*2+1) of each kstep
    const uint4* w1q = gW1q + wn * 2 * 32 + lane;
    const uint4* w2q = gW2q + wn * 2 * 32 + lane;

    const int stride = gridDim.x;
    int t = blockIdx.x;
    if (t >= N_TILES) return;

    // ---- prologue: gather tile t into buf 0 ----
    {
        int node = ghalf ? __ldg(cols + t * TILE_E + ge) : __ldg(rows + t * TILE_E + ge);
        if (tid < 16) cpa16(sb + SM_ROW + tid * 16, rows + t * TILE_E + tid * 4);
        const char* src = (const char*)(gF + (size_t)node * FDIM + gseg * 64);
        uint32_t dst = sb + SM_A + gDstOff;
        #pragma unroll
        for (int i = 0; i < 8; i++) cpa16(dst + i * 16, src + i * 16);
        CP_COMMIT();
    }
    int nodeAhead = 0;
    {
        int tn = t + stride;
        if (tn < N_TILES)
            nodeAhead = ghalf ? __ldg(cols + tn * TILE_E + ge) : __ldg(rows + tn * TILE_E + ge);
    }
    CP_WAIT0();
    __syncthreads();

    // ---- hoist per-lane biases into registers (tile-invariant) ----
    float b1h0[4], b1h1[4], b20[4], b21[4];
    #pragma unroll
    for (int nf = 0; nf < 4; nf++) {
        int c = wn * 32 + nf * 8 + ecol;
        b1h0[nf] = 0.5f * sB1[c];
        b1h1[nf] = 0.5f * sB1[c + 1];
        b20[nf]  = sB2[c];
        b21[nf]  = sB2[c + 1];
    }

    int cur = 0;
    for (;;) {
        const int t_next = t + stride;
        const bool haveNext = (t_next < N_TILES);

        // ---- issue prefetch of tile t+1 into buf cur^1 ----
        if (haveNext) {
            if (tid < 16) cpa16(sb + SM_ROW + (cur ^ 1) * 256 + tid * 16,
                                rows + t_next * TILE_E + tid * 4);
            const char* src = (const char*)(gF + (size_t)nodeAhead * FDIM + gseg * 64);
            uint32_t dst = sb + SM_A + (cur ^ 1) * ABUF + gDstOff;
            #pragma unroll
            for (int i = 0; i < 8; i++) cpa16(dst + i * 16, src + i * 16);
            CP_COMMIT();
            int t2 = t_next + stride;
            if (t2 < N_TILES)
                nodeAhead = ghalf ? __ldg(cols + t2 * TILE_E + ge)
                                  : __ldg(rows + t2 * TILE_E + ge);
        }

        const uint32_t aBase = sb + SM_A + cur * ABUF;
        const int* sRow = sRowB + cur * 64;

        // ---- GEMM1: [64,256] @ W1[256,128], fp16, paired-uint4 B frags ----
        float4 acc[2][4];
        #pragma unroll
        for (int m = 0; m < 2; m++)
            #pragma unroll
            for (int nf = 0; nf < 4; nf++) acc[m][nf] = make_float4(0.f, 0.f, 0.f, 0.f);

        uint2 bf[2][4];
        {
            uint4 q0 = __ldg(w1q);
            uint4 q1 = __ldg(w1q + 32);
            bf[0][0] = make_uint2(q0.x, q0.y); bf[0][1] = make_uint2(q0.z, q0.w);
            bf[0][2] = make_uint2(q1.x, q1.y); bf[0][3] = make_uint2(q1.z, q1.w);
        }

        #pragma unroll 2
        for (int ks = 0; ks < 16; ks++) {
            const int c = ks & 1, nx = c ^ 1;
            uint32_t ah[2][4];
            #pragma unroll
            for (int m = 0; m < 2; m++) {
                uint32_t ab = aBase +
                    (uint32_t)(((wm * 32 + m * 16 + arow) * LDA + ks * 16 + acolk) * 2);
                ldmx4(ah[m], ab);
            }
            if (ks < 15) {
                uint4 q0 = __ldg(w1q + (ks + 1) * 8 * 32);
                uint4 q1 = __ldg(w1q + (ks + 1) * 8 * 32 + 32);
                bf[nx][0] = make_uint2(q0.x, q0.y); bf[nx][1] = make_uint2(q0.z, q0.w);
                bf[nx][2] = make_uint2(q1.x, q1.y); bf[nx][3] = make_uint2(q1.z, q1.w);
            }
            #pragma unroll
            for (int nf = 0; nf < 4; nf++)
                #pragma unroll
                for (int m = 0; m < 2; m++)
                    mma_f16(acc[m][nf], ah[m], bf[c][nf]);
        }

        // ---- epilogue 1: h = sigmoid(D1 + bm1) via tanh.f16x2 -> sH ----
        #pragma unroll
        for (int m = 0; m < 2; m++)
            #pragma unroll
            for (int nf = 0; nf < 4; nf++) {
                int r0 = wm * 32 + m * 16 + erow;
                int c  = wn * 32 + nf * 8 + ecol;
                *(uint32_t*)(sH + r0 * LDH + c) =
                    sig2_h2(fmaf(acc[m][nf].x, 0.5f, b1h0[nf]),
                            fmaf(acc[m][nf].y, 0.5f, b1h1[nf]));
                *(uint32_t*)(sH + (r0 + 8) * LDH + c) =
                    sig2_h2(fmaf(acc[m][nf].z, 0.5f, b1h0[nf]),
                            fmaf(acc[m][nf].w, 0.5f, b1h1[nf]));
            }
        // GEMM2 reads only rows of its own wm half; those rows are written
        // only by the 4 warps sharing wm -> narrow named barrier.
        BAR_SYNC(1 + wm);

        // ---- GEMM2: [64,128] @ W2[128,128], fp16 ----
        float4 acc2[2][4];
        #pragma unroll
        for (int m = 0; m < 2; m++)
            #pragma unroll
            for (int nf = 0; nf < 4; nf++) acc2[m][nf] = make_float4(0.f, 0.f, 0.f, 0.f);

        {
            uint4 q0 = __ldg(w2q);
            uint4 q1 = __ldg(w2q + 32);
            bf[0][0] = make_uint2(q0.x, q0.y); bf[0][1] = make_uint2(q0.z, q0.w);
            bf[0][2] = make_uint2(q1.x, q1.y); bf[0][3] = make_uint2(q1.z, q1.w);
        }

        #pragma unroll 2
        for (int ks = 0; ks < 8; ks++) {
            const int c = ks & 1, nx = c ^ 1;
            uint32_t ah[2][4];
            #pragma unroll
            for (int m = 0; m < 2; m++) {
                uint32_t ab = sb + SM_H +
                    (uint32_t)(((wm * 32 + m * 16 + arow) * LDH + ks * 16 + acolk) * 2);
                ldmx4(ah[m], ab);
            }
            if (ks < 7) {
                uint4 q0 = __ldg(w2q + (ks + 1) * 8 * 32);
                uint4 q1 = __ldg(w2q + (ks + 1) * 8 * 32 + 32);
                bf[nx][0] = make_uint2(q0.x, q0.y); bf[nx][1] = make_uint2(q0.z, q0.w);
                bf[nx][2] = make_uint2(q1.x, q1.y); bf[nx][3] = make_uint2(q1.z, q1.w);
            }
            #pragma unroll
            for (int nf = 0; nf < 4; nf++)
                #pragma unroll
                for (int m = 0; m < 2; m++)
                    mma_f16(acc2[m][nf], ah[m], bf[c][nf]);
        }

        // ---- epilogue 2: softsign + red2 scatter into g_agg ----
        #pragma unroll
        for (int m = 0; m < 2; m++) {
            int r0 = wm * 32 + m * 16 + erow;
            int n0 = sRow[r0];
            int n1 = sRow[r0 + 8];
            #pragma unroll
            for (int nf = 0; nf < 4; nf++) {
                int cb = wn * 32 + nf * 8 + ecol;
                red2(g_agg + (size_t)n0 * FDIM + cb,
                     softsignf_(acc2[m][nf].x + b20[nf]),
                     softsignf_(acc2[m][nf].y + b21[nf]));
                red2(g_agg + (size_t)n1 * FDIM + cb,
                     softsignf_(acc2[m][nf].z + b20[nf]),
                     softsignf_(acc2[m][nf].w + b21[nf]));
            }
        }

        if (!haveNext) break;
        CP_WAIT0();
        __syncthreads();   // sA/sRow buf cur^1 ready; sH reuse safe (same-wm
                           // writers passed BAR above, cross-wm don't share sH rows)
        t = t_next;
        cur ^= 1;
    }
}

// ===========================================================================
// Node kernel (R7 version, unchanged)
// ===========================================================================
#define TEN 64
#define NLDH 132
#define NLDN 388

__global__ void __launch_bounds__(256, 2)
node_kernel(const float* __restrict__ features,
            const float* __restrict__ time_emb,
            const float* __restrict__ Wf1,
            const float* __restrict__ bf1,
            const float* __restrict__ Wf2,
            const float* __restrict__ bf2,
            float* __restrict__ out)
{
    extern __shared__ float smemf[];
    float* sIn = smemf;

    const int tid = threadIdx.x;
    const int tx  = tid & 31;
    const int ty  = tid >> 5;
    const int n0  = blockIdx.x * TEN;

    for (int n = ty; n < TEN; n += 8) {
        int node = n0 + n;
        float4 a, g, t;
        if (node < N_NODES) {
            a = __ldg((const float4*)(features + (size_t)node * FDIM) + tx);
            g = *((const float4*)(g_agg + (size_t)node * FDIM) + tx);
            t = __ldg((const float4*)(time_emb + (size_t)node * FDIM) + tx);
        } else {
            a = g = t = make_float4(0.f, 0.f, 0.f, 0.f);
        }
        *(float4*)&sIn[n * NLDN + tx * 4] =
            make_float4(sigmoidf_(a.x), sigmoidf_(a.y), sigmoidf_(a.z), sigmoidf_(a.w));
        *(float4*)&sIn[n * NLDN + FDIM + tx * 4] =
            make_float4(sigmoidf_(g.x), sigmoidf_(g.y), sigmoidf_(g.z), sigmoidf_(g.w));
        *(float4*)&sIn[n * NLDN + 2 * FDIM + tx * 4] =
            make_float4(sigmoidf_(t.x), sigmoidf_(t.y), sigmoidf_(t.z), sigmoidf_(t.w));
    }
    __syncthreads();

    u64 acc[8][2];
    #pragma unroll
    for (int e = 0; e < 8; e++) { acc[e][0] = 0ull; acc[e][1] = 0ull; }

    const float* wBase = Wf1 + tx * 4;
    const float* aBase = sIn + (ty * 8) * NLDN;

    #pragma unroll 2
    for (int k = 0; k < 3 * FDIM; k += 4) {
        u64 w0a, w0b, w1a, w1b, w2a, w2b, w3a, w3b;
        ldg2x2(wBase + (k + 0) * FDIM, w0a, w0b);
        ldg2x2(wBase + (k + 1) * FDIM, w1a, w1b);
        ldg2x2(wBase + (k + 2) * FDIM, w2a, w2b);
        ldg2x2(wBase + (k + 3) * FDIM, w3a, w3b);
        #pragma unroll
        for (int e = 0; e < 8; e++) {
            float4 a = *(const float4*)(aBase + e * NLDN + k);
            u64 a0 = pack2(a.x), a1 = pack2(a.y), a2 = pack2(a.z), a3 = pack2(a.w);
            ffma2(acc[e][0], a0, w0a); ffma2(acc[e][1], a0, w0b);
            ffma2(acc[e][0], a1, w1a); ffma2(acc[e][1], a1, w1b);
            ffma2(acc[e][0], a2, w2a); ffma2(acc[e][1], a2, w2b);
            ffma2(acc[e][0], a3, w3a); ffma2(acc[e][1], a3, w3b);
        }
    }
    __syncthreads();

    float4 b1 = __ldg((const float4*)bf1 + tx);
    float* sHf = smemf;
    #pragma unroll
    for (int e = 0; e < 8; e++) {
        float x0, x1, x2, x3;
        unpack2(acc[e][0], x0, x1);
        unpack2(acc[e][1], x2, x3);
        float4 h;
        h.x = sigmoidf_(x0 + b1.x);
        h.y = sigmoidf_(x1 + b1.y);
        h.z = sigmoidf_(x2 + b1.z);
        h.w = sigmoidf_(x3 + b1.w);
        *(float4*)&sHf[(ty * 8 + e) * NLDH + tx * 4] = h;
    }
    __syncthreads();

    u64 acc2[8][2];
    #pragma unroll
    for (int e = 0; e < 8; e++) { acc2[e][0] = 0ull; acc2[e][1] = 0ull; }

    const float* w2Base = Wf2 + tx * 4;
    const float* hBase  = sHf + (ty * 8) * NLDH;

    #pragma unroll 2
    for (int k = 0; k < FDIM; k += 4) {
        u64 w0a, w0b, w1a, w1b, w2a, w2b, w3a, w3b;
        ldg2x2(w2Base + (k + 0) * FDIM, w0a, w0b);
        ldg2x2(w2Base + (k + 1) * FDIM, w1a, w1b);
        ldg2x2(w2Base + (k + 2) * FDIM, w2a, w2b);
        ldg2x2(w2Base + (k + 3) * FDIM, w3a, w3b);
        #pragma unroll
        for (int e = 0; e < 8; e++) {
            float4 a = *(const float4*)(hBase + e * NLDH + k);
            u64 a0 = pack2(a.x), a1 = pack2(a.y), a2 = pack2(a.z), a3 = pack2(a.w);
            ffma2(acc2[e][0], a0, w0a); ffma2(acc2[e][1], a0, w0b);
            ffma2(acc2[e][0], a1, w1a); ffma2(acc2[e][1], a1, w1b);
            ffma2(acc2[e][0], a2, w2a); ffma2(acc2[e][1], a2, w2b);
            ffma2(acc2[e][0], a3, w3a); ffma2(acc2[e][1], a3, w3b);
        }
    }

    float4 b2 = __ldg((const float4*)bf2 + tx);
    #pragma unroll
    for (int e = 0; e < 8; e++) {
        int node = n0 + ty * 8 + e;
        if (node < N_NODES) {
            float x0, x1, x2, x3;
            unpack2(acc2[e][0], x0, x1);
            unpack2(acc2[e][1], x2, x3);
            float4 o;
            o.x = softsignf_(x0 + b2.x);
            o.y = softsignf_(x1 + b2.y);
            o.z = softsignf_(x2 + b2.z);
            o.w = softsignf_(x3 + b2.w);
            *(float4*)(out + (size_t)node * FDIM + tx * 4) = o;
        }
    }
}

// ===========================================================================
extern "C" void kernel_launch(void* const* d_in, const int* in_sizes, int n_in,
                              void* d_out, int out_size)
{
    const float* features = (const float*)d_in[0];
    const int*   rows     = (const int*)  d_in[1];
    const int*   cols     = (const int*)  d_in[2];
    const float* time_emb = (const float*)d_in[3];
    const float* Wm1      = (const float*)d_in[4];
    const float* bm1      = (const float*)d_in[5];
    const float* Wm2      = (const float*)d_in[6];
    const float* bm2      = (const float*)d_in[7];
    const float* Wf1      = (const float*)d_in[8];
    const float* bf1      = (const float*)d_in[9];
    const float* Wf2      = (const float*)d_in[10];
    const float* bf2      = (const float*)d_in[11];
    float* out = (float*)d_out;

    const int node_smem = TEN * NLDN * sizeof(float);
    cudaFuncSetAttribute(edge_mma_kernel, cudaFuncAttributeMaxDynamicSharedMemorySize, SM_TOTAL);
    cudaFuncSetAttribute(node_kernel,     cudaFuncAttributeMaxDynamicSharedMemorySize, node_smem);

    void* aggp = nullptr;
    cudaGetSymbolAddress(&aggp, g_agg);
    cudaMemsetAsync(aggp, 0, (size_t)N_NODES * FDIM * sizeof(float));

    uint4 *w1q, *w2q;
    cudaGetSymbolAddress((void**)&w1q, gW1q);
    cudaGetSymbolAddress((void**)&w2q, gW2q);

    prep_features<<<(N_NODES * FDIM + 255) / 256, 256>>>(features);
    prep_wfrag<<<32, 256>>>(Wm1, 16, w1q);
    prep_wfrag<<<16, 256>>>(Wm2,  8, w2q);

    edge_mma_kernel<<<296, 256, SM_TOTAL>>>(rows, cols, bm1, bm2);

    node_kernel<<<(N_NODES + TEN - 1) / TEN, 256, node_smem>>>(features, time_emb,
                                                               Wf1, bf1, Wf2, bf2, out);
}